// round 4
// baseline (speedup 1.0000x reference)
#include <cuda_runtime.h>
#include <math.h>

#define D_IN   256
#define D_EMB  512
#define K_CB   2048
#define T_MAX  65536

#define TOK_TILE 64
#define CB_TILE  128
#define KK_CHUNK 64
#define FPAD 68
#define APAD 132
#define K2_SMEM ((D_IN * FPAD + KK_CHUNK * APAD) * 4 + 64 * 4 + 64 * 16 * 4)
#define MARGIN 1.4e-4f
#define NB_EXACT 2048

// ---------------- scratch (device globals; no allocations allowed) -----------
__device__ __align__(16) float g_AT[D_IN * K_CB];   // A transposed [i][k]
__device__ __align__(16) float g_Q[K_CB * D_IN];    // fused output codebook [k][j]
__device__ float g_c[K_CB];
__device__ float g_se[K_CB];                        // fp32 sum of e^2 per codeword
__device__ float g_b1eff[D_EMB];
__device__ int g_idx[T_MAX];
__device__ unsigned int g_hist[K_CB];
__device__ double g_partial[8192];
__device__ int g_ccount[T_MAX];
__device__ unsigned short g_cand[T_MAX][16];
__device__ int g_needy[T_MAX];
__device__ int g_nneedy;

// ---------------- K0: b1eff, zero hist/counters ------------------------------
__global__ void k0_init(const float* __restrict__ W1, const float* __restrict__ b1,
                        const float* __restrict__ beta1) {
    int t = blockIdx.x * blockDim.x + threadIdx.x;
    if (t < D_EMB) {
        float s = b1[t];
        for (int i = 0; i < D_IN; i++) s = fmaf(beta1[i], W1[t * D_IN + i], s);
        g_b1eff[t] = s;
    }
    if (t < K_CB) g_hist[t] = 0u;
    if (t == 0) g_nneedy = 0;
}

// ---------------- K1: precompute AT and Q (approx path, tolerance-fine) ------
#define K1_ROWS 16
#define EPAD 20
__global__ __launch_bounds__(256) void k1_precompute(
    const float* __restrict__ emb, const float* __restrict__ W1,
    const float* __restrict__ W2, const float* __restrict__ g1v,
    const float* __restrict__ g2v, const float* __restrict__ beta2,
    const float* __restrict__ b2) {
    __shared__ float sE[D_EMB * EPAD];
    __shared__ float sG2[D_EMB];
    __shared__ float sB2[D_EMB];
    const int t = threadIdx.x;
    const int k0 = blockIdx.x * K1_ROWS;
    const float bn_s = rsqrtf(1.0f + 1e-5f);

    {
        int r = t & 15, ov = t >> 4;
        for (int pass = 0; pass < 8; pass++) {
            int o4 = ov + pass * 16;
            float4 v = *(const float4*)&emb[(size_t)(k0 + r) * D_EMB + o4 * 4];
            sE[(o4 * 4 + 0) * EPAD + r] = v.x;
            sE[(o4 * 4 + 1) * EPAD + r] = v.y;
            sE[(o4 * 4 + 2) * EPAD + r] = v.z;
            sE[(o4 * 4 + 3) * EPAD + r] = v.w;
        }
    }
    for (int i = t; i < D_EMB; i += 256) {
        sG2[i] = g2v[i] * bn_s;
        sB2[i] = beta2[i];
    }
    __syncthreads();

    const int j = t;
    float accA[16], accQ[16];
    float qc = 0.f;
#pragma unroll
    for (int r = 0; r < 16; r++) { accA[r] = 0.f; accQ[r] = 0.f; }

#pragma unroll 2
    for (int o = 0; o < D_EMB; o++) {
        float w1 = W1[o * D_IN + j];
        float w2 = W2[j * D_EMB + o];
        float gw = sG2[o] * w2;
        qc = fmaf(sB2[o], w2, qc);
        const float* e = &sE[o * EPAD];
        float4 e0 = *(const float4*)(e + 0);
        float4 e1 = *(const float4*)(e + 4);
        float4 e2 = *(const float4*)(e + 8);
        float4 e3 = *(const float4*)(e + 12);
        float ev[16] = {e0.x,e0.y,e0.z,e0.w, e1.x,e1.y,e1.z,e1.w,
                        e2.x,e2.y,e2.z,e2.w, e3.x,e3.y,e3.z,e3.w};
#pragma unroll
        for (int r = 0; r < 16; r++) {
            accA[r] = fmaf(ev[r], w1, accA[r]);
            accQ[r] = fmaf(ev[r], gw, accQ[r]);
        }
    }
    float g1j = g1v[j] * bn_s;
    float b2j = b2[j];
#pragma unroll
    for (int r4 = 0; r4 < 4; r4++) {
        float4 va;
        va.x = g1j * accA[r4*4+0]; va.y = g1j * accA[r4*4+1];
        va.z = g1j * accA[r4*4+2]; va.w = g1j * accA[r4*4+3];
        *(float4*)&g_AT[(size_t)j * K_CB + k0 + r4 * 4] = va;
    }
#pragma unroll
    for (int r = 0; r < 16; r++)
        g_Q[(size_t)(k0 + r) * D_IN + j] = accQ[r] + qc + b2j;
}

// ---------------- K1b: c[k] (approx) and se[k] (fp32 sum of squares) ---------
__global__ __launch_bounds__(256) void k1b_c(const float* __restrict__ emb) {
    int w = blockIdx.x * 8 + (threadIdx.x >> 5);
    int lane = threadIdx.x & 31;
    if (w >= K_CB) return;
    float s = 0.f, se = 0.f;
    for (int o = lane; o < D_EMB; o += 32) {
        float ev = emb[(size_t)w * D_EMB + o];
        s = fmaf(ev, g_b1eff[o] - 0.5f * ev, s);
        se = __fadd_rn(se, __fmul_rn(ev, ev));
    }
#pragma unroll
    for (int d = 16; d >= 1; d >>= 1) {
        s += __shfl_xor_sync(0xffffffffu, s, d);
        se = __fadd_rn(se, __shfl_xor_sync(0xffffffffu, se, d));
    }
    if (lane == 0) { g_c[w] = s; g_se[w] = se; }
}

// ---------------- K2: approx scores + candidate extraction -------------------
// s[t,k] = flat[t,:].A[k,:] + c[k] ~= x.e - 0.5*||e||^2 (error ~1e-7)
// All d-argmin achievers satisfy s >= s_max - 1.23e-4; MARGIN=1.4e-4 covers it.
__global__ __launch_bounds__(256, 2) void k2_argmax(const float* __restrict__ inputs) {
    extern __shared__ float smem[];
    float* sFlat = smem;                 // [256 kk][FPAD]
    float* sA = smem + D_IN * FPAD;      // [64 kk][APAD]
    int* sCnt = (int*)(smem + D_IN * FPAD + KK_CHUNK * APAD);
    int* sCand = sCnt + 64;              // [64][16]

    const int t = threadIdx.x;
    const int t0 = blockIdx.x * TOK_TILE;

    if (t < 64) sCnt[t] = 0;

    {
        int tok = t & 63;
        int qb = t >> 6;
        const float* rowp = inputs + (size_t)(t0 + tok) * D_IN;
#pragma unroll
        for (int pass = 0; pass < 16; pass++) {
            int q = qb + pass * 4;
            float4 v = *(const float4*)(rowp + q * 4);
            sFlat[(q * 4 + 0) * FPAD + tok] = v.x;
            sFlat[(q * 4 + 1) * FPAD + tok] = v.y;
            sFlat[(q * 4 + 2) * FPAD + tok] = v.z;
            sFlat[(q * 4 + 3) * FPAD + tok] = v.w;
        }
    }

    const int cbg = t & 15;
    const int tokg = t >> 4;
    float v0[4], v1[4], v2[4];
    int i0[4], i1[4], i2[4];
#pragma unroll
    for (int u = 0; u < 4; u++) {
        v0[u] = v1[u] = v2[u] = -INFINITY;
        i0[u] = i1[u] = i2[u] = 0;
    }

    for (int cb0 = 0; cb0 < K_CB; cb0 += CB_TILE) {
        float acc[8][4];
#pragma unroll
        for (int i = 0; i < 8; i++)
#pragma unroll
            for (int u = 0; u < 4; u++) acc[i][u] = 0.f;

        for (int kk0 = 0; kk0 < D_IN; kk0 += KK_CHUNK) {
            __syncthreads();
            {
                int cv = t & 31;
                int kr = t >> 5;
#pragma unroll
                for (int pass = 0; pass < 8; pass++) {
                    int kk = kr + pass * 8;
                    float4 v = *(const float4*)&g_AT[(size_t)(kk0 + kk) * K_CB + cb0 + cv * 4];
                    *(float4*)&sA[kk * APAD + cv * 4] = v;
                }
            }
            __syncthreads();
#pragma unroll 2
            for (int kk = 0; kk < KK_CHUNK; kk++) {
                const float4 a  = *(const float4*)(sFlat + (kk0 + kk) * FPAD + (tokg << 2));
                const float4 p0 = *(const float4*)(sA + kk * APAD + (cbg << 3));
                const float4 p1 = *(const float4*)(sA + kk * APAD + (cbg << 3) + 4);
                float av[4] = {a.x, a.y, a.z, a.w};
                float bv[8] = {p0.x, p0.y, p0.z, p0.w, p1.x, p1.y, p1.z, p1.w};
#pragma unroll
                for (int i = 0; i < 8; i++)
#pragma unroll
                    for (int u = 0; u < 4; u++)
                        acc[i][u] = fmaf(bv[i], av[u], acc[i][u]);
            }
        }
        // top-3 per (thread, token) insertion
#pragma unroll
        for (int i = 0; i < 8; i++) {
            int cb = cb0 + cbg * 8 + i;
            float ci = g_c[cb];
#pragma unroll
            for (int u = 0; u < 4; u++) {
                float s = acc[i][u] + ci;
                if (s > v2[u]) {
                    if (s > v1[u]) {
                        if (s > v0[u]) {
                            v2[u]=v1[u]; i2[u]=i1[u]; v1[u]=v0[u]; i1[u]=i0[u];
                            v0[u]=s; i0[u]=cb;
                        } else { v2[u]=v1[u]; i2[u]=i1[u]; v1[u]=s; i1[u]=cb; }
                    } else { v2[u]=s; i2[u]=cb; }
                }
            }
        }
    }

    // per-token global max over the 16 cb groups, then emit candidates
#pragma unroll
    for (int u = 0; u < 4; u++) {
        float g = v0[u];
#pragma unroll
        for (int d = 8; d >= 1; d >>= 1)
            g = fmaxf(g, __shfl_down_sync(0xffffffffu, g, d, 16));
        g = __shfl_sync(0xffffffffu, g, 0, 16);
        float thr = g - MARGIN;
        int tokl = tokg * 4 + u;
        if (v0[u] >= thr) { int p = atomicAdd(&sCnt[tokl], 1); if (p < 16) sCand[tokl * 16 + p] = i0[u]; }
        if (v1[u] >= thr) { int p = atomicAdd(&sCnt[tokl], 1); if (p < 16) sCand[tokl * 16 + p] = i1[u]; }
        if (v2[u] >= thr) { int p = atomicAdd(&sCnt[tokl], 1); if (p < 16) sCand[tokl * 16 + p] = i2[u]; }
    }
    __syncthreads();
    if (t < 64) {
        int cnt = sCnt[t];
        int tok = t0 + t;
        g_ccount[tok] = cnt;
        if (cnt == 1) {
            int k = sCand[t * 16];
            g_idx[tok] = k;
            atomicAdd(&g_hist[k], 1u);
        } else {
            int m = cnt < 16 ? cnt : 16;
            for (int j = 0; j < m; j++) g_cand[tok][j] = (unsigned short)sCand[t * 16 + j];
            int p = atomicAdd(&g_nneedy, 1);
            g_needy[p] = tok;
        }
    }
}

// ---------------- K_exact: jax-emulated fp32 distances for contested tokens --
// x_o = seqFMA_i(xin_i * W1[o,i]) + b1[o];  m_k = seqFMA_o(x_o * e[k,o])
// d_k = fl(fl(sx + se_k) - 2*m_k); argmin, ties -> lowest k.
__global__ __launch_bounds__(256) void k_exact(
    const float* __restrict__ inputs, const float* __restrict__ g1v,
    const float* __restrict__ beta1, const float* __restrict__ W1,
    const float* __restrict__ b1, const float* __restrict__ emb, float S) {
    __shared__ float sXin[D_IN];
    __shared__ float sX[D_EMB];
    __shared__ float sRed[256];
    __shared__ int sRedI[256];
    __shared__ float sSx;
    const int tid = threadIdx.x;
    const int n = g_nneedy;
    for (int it = blockIdx.x; it < n; it += gridDim.x) {
        int t = g_needy[it];
        // xin = fl(fl(flat * fl(g1*S)) + beta1)
        {
            float f = inputs[(size_t)t * D_IN + tid];
            float sc = __fmul_rn(g1v[tid], S);
            sXin[tid] = __fadd_rn(__fmul_rn(f, sc), beta1[tid]);
        }
        __syncthreads();
        // x rows: sequential fp32 FMA chain over i=0..255
#pragma unroll
        for (int h = 0; h < 2; h++) {
            int o = tid + h * 256;
            const float4* w4 = (const float4*)(W1 + (size_t)o * D_IN);
            float a = 0.f;
#pragma unroll 4
            for (int i4 = 0; i4 < D_IN / 4; i4++) {
                float4 w = w4[i4];
                a = fmaf(sXin[i4 * 4 + 0], w.x, a);
                a = fmaf(sXin[i4 * 4 + 1], w.y, a);
                a = fmaf(sXin[i4 * 4 + 2], w.z, a);
                a = fmaf(sXin[i4 * 4 + 3], w.w, a);
            }
            sX[o] = __fadd_rn(a, b1[o]);
        }
        __syncthreads();
        // sx (fp32, order-free by grid-shift invariance)
        {
            float p = __fadd_rn(__fmul_rn(sX[tid], sX[tid]),
                                __fmul_rn(sX[tid + 256], sX[tid + 256]));
#pragma unroll
            for (int d = 16; d >= 1; d >>= 1)
                p = __fadd_rn(p, __shfl_xor_sync(0xffffffffu, p, d));
            if ((tid & 31) == 0) sRed[tid >> 5] = p;
            __syncthreads();
            if (tid == 0) {
                float s = 0.f;
#pragma unroll
                for (int w = 0; w < 8; w++) s = __fadd_rn(s, sRed[w]);
                sSx = s;
            }
            __syncthreads();
        }
        float sx = sSx;
        int cnt = g_ccount[t];
        int C = (cnt <= 16) ? cnt : K_CB;   // overflow -> exact full scan
        float bd = INFINITY;
        int bk = 0x7fffffff;
        for (int ci = tid; ci < C; ci += 256) {
            int k = (cnt <= 16) ? (int)g_cand[t][ci] : ci;
            const float4* e4 = (const float4*)(emb + (size_t)k * D_EMB);
            float m = 0.f;
#pragma unroll 4
            for (int o4 = 0; o4 < D_EMB / 4; o4++) {
                float4 e = e4[o4];
                m = fmaf(sX[o4 * 4 + 0], e.x, m);
                m = fmaf(sX[o4 * 4 + 1], e.y, m);
                m = fmaf(sX[o4 * 4 + 2], e.z, m);
                m = fmaf(sX[o4 * 4 + 3], e.w, m);
            }
            float d = __fsub_rn(__fadd_rn(sx, g_se[k]), __fmul_rn(2.0f, m));
            if (d < bd || (d == bd && k < bk)) { bd = d; bk = k; }
        }
        sRed[tid] = bd; sRedI[tid] = bk;
        __syncthreads();
        for (int d = 128; d >= 1; d >>= 1) {
            if (tid < d) {
                float od = sRed[tid + d]; int ok = sRedI[tid + d];
                if (od < sRed[tid] || (od == sRed[tid] && ok < sRedI[tid])) {
                    sRed[tid] = od; sRedI[tid] = ok;
                }
            }
            __syncthreads();
        }
        if (tid == 0) { g_idx[t] = sRedI[0]; atomicAdd(&g_hist[sRedI[0]], 1u); }
        __syncthreads();
    }
}

// ---------------- K3: gather Q[idx], straight-through output, SSE partials ---
__global__ __launch_bounds__(256) void k3_gather(const float* __restrict__ inputs,
                                                 float* __restrict__ outq) {
    const int t = threadIdx.x;
    float s = 0.f;
#pragma unroll
    for (int r = 0; r < 8; r++) {
        int gid = blockIdx.x * 2048 + r * 256 + t;
        int tok = gid >> 8;
        int j = gid & 255;
        int idx = g_idx[tok];
        float q = g_Q[(size_t)idx * D_IN + j];
        float x = inputs[gid];
        float d = __fsub_rn(q, x);
        outq[gid] = __fadd_rn(x, d);
        s = fmaf(d, d, s);
    }
#pragma unroll
    for (int d = 16; d >= 1; d >>= 1) s += __shfl_xor_sync(0xffffffffu, s, d);
    __shared__ float wsum[8];
    if ((t & 31) == 0) wsum[t >> 5] = s;
    __syncthreads();
    if (t == 0) {
        float tot = 0.f;
#pragma unroll
        for (int w = 0; w < 8; w++) tot += wsum[w];
        g_partial[blockIdx.x] = (double)tot;
    }
}

// ---------------- K4: loss + usage -------------------------------------------
__global__ void k4_final(float* __restrict__ out, int T) {
    int t = blockIdx.x * 256 + threadIdx.x;
    if (t < K_CB) out[1 + (size_t)T * D_IN + t] = (float)g_hist[t] * (1.0f / (float)T);
    if (blockIdx.x == 0) {
        double s = 0.0;
        for (int i = threadIdx.x; i < 8192; i += 256) s += g_partial[i];
        __shared__ double sh[256];
        sh[threadIdx.x] = s;
        __syncthreads();
        for (int d = 128; d >= 1; d >>= 1) {
            if (threadIdx.x < d) sh[threadIdx.x] += sh[threadIdx.x + d];
            __syncthreads();
        }
        if (threadIdx.x == 0)
            out[0] = (float)(1.25 * sh[0] / ((double)T * (double)D_IN));
    }
}

// ---------------- launch ------------------------------------------------------
extern "C" void kernel_launch(void* const* d_in, const int* in_sizes, int n_in,
                              void* d_out, int out_size) {
    const float* inputs    = (const float*)d_in[0];
    const float* bn1_gamma = (const float*)d_in[1];
    const float* bn1_beta  = (const float*)d_in[2];
    const float* W1        = (const float*)d_in[3];
    const float* b1        = (const float*)d_in[4];
    const float* emb       = (const float*)d_in[5];
    const float* bn2_gamma = (const float*)d_in[6];
    const float* bn2_beta  = (const float*)d_in[7];
    const float* W2        = (const float*)d_in[8];
    const float* b2        = (const float*)d_in[9];
    float* out = (float*)d_out;
    const int T = in_sizes[0] / D_IN;   // 65536

    // jax: bn_scale = fl(1 / fl(sqrt(fl(1.0 + 1e-5))))  (all fp32 rn)
    float af = (float)(1.0 + 1e-5);
    float S = 1.0f / sqrtf(af);

    k0_init<<<8, 256>>>(W1, b1, bn1_beta);
    k1_precompute<<<K_CB / K1_ROWS, 256>>>(emb, W1, W2, bn1_gamma, bn2_gamma, bn2_beta, b2);
    k1b_c<<<K_CB / 8, 256>>>(emb);
    cudaFuncSetAttribute(k2_argmax, cudaFuncAttributeMaxDynamicSharedMemorySize, K2_SMEM);
    k2_argmax<<<T / TOK_TILE, 256, K2_SMEM>>>(inputs);
    k_exact<<<NB_EXACT, 256>>>(inputs, bn1_gamma, bn1_beta, W1, b1, emb, S);
    k3_gather<<<8192, 256>>>(inputs, out + 1);
    k4_final<<<8, 256>>>(out, T);
}